// round 1
// baseline (speedup 1.0000x reference)
#include <cuda_runtime.h>

// Problem constants
#define B_   4
#define H_   16
#define N_   8192
#define DE   64          // D == E == 64
#define SPLIT 8          // N-splits per (b,h); grid = (SPLIT, B*H)
#define TROWS 64         // rows per tile
#define KST  68          // smem row stride (floats): 272B, 16B-aligned, reduces conflicts
#define EPSV 1e-10f

#define KV_OFF   ((long long)B_ * H_ * N_ * DE)                 // 33554432
#define NORM_OFF (KV_OFF + (long long)B_ * H_ * DE * DE)        // +262144
#define SMEM_BYTES ((3 * 64 * KST + 4096 + 3 * 64) * 4)         // 69376 B

// ---------------------------------------------------------------------------
// Init: seed new_kv / new_norm output regions with past_kv / past_norm,
// so the main kernel can atomicAdd partial sums into them.
// ---------------------------------------------------------------------------
__global__ void fw_init(const float* __restrict__ pkv,
                        const float* __restrict__ pnorm,
                        float* __restrict__ dout) {
    int i = blockIdx.x * blockDim.x + threadIdx.x;
    if (i < B_ * H_ * DE * DE) dout[KV_OFF + i]   = pkv[i];
    if (i < B_ * H_ * DE)      dout[NORM_OFF + i] = pnorm[i];
}

__device__ __forceinline__ float elu1(float x) {
    // jax.nn.elu(x) + 1 = x+1 (x>0) else exp(x)
    return x > 0.f ? x + 1.f : __expf(x);
}

// ---------------------------------------------------------------------------
// Main fused kernel. One CTA = one (b,h) pair x one N-chunk of 1024 rows.
// 256 threads: tx = tid&15 -> 4 output cols (e), ty = tid>>4 -> 4 rows (or 4 d's).
// ---------------------------------------------------------------------------
__global__ __launch_bounds__(256, 2)
void fw_main(const float* __restrict__ keys,
             const float* __restrict__ values,
             const float* __restrict__ queries,
             const float* __restrict__ outin,
             const float* __restrict__ pkv,
             const float* __restrict__ pnorm,
             const float* __restrict__ hg,
             float* __restrict__ dout)
{
    extern __shared__ float sm[];
    float* k_s    = sm;                  // [64][KST]
    float* q_s    = k_s + 64 * KST;      // [64][KST]
    float* v_s    = q_s + 64 * KST;      // [64][KST]
    float* pkv_s  = v_s + 64 * KST;      // [64][64]
    float* norm_s = pkv_s + 4096;        // [64]
    float* rdk_s  = norm_s + 64;         // [64] 1/denom_k per row
    float* rdq_s  = rdk_s + 64;          // [64] 1/denom_q per row

    const int tid   = threadIdx.x;
    const int split = blockIdx.x;
    const int bh    = blockIdx.y;
    const int h     = bh & (H_ - 1);

    const float gate  = 1.f / (1.f + __expf(-hg[h]));
    const float gate1 = 1.f - gate;

    // Stage past_kv and past_norm into smem
    {
        const float4* pg = (const float4*)(pkv + (long long)bh * DE * DE);
        for (int i = tid; i < DE * DE / 4; i += 256)
            ((float4*)pkv_s)[i] = pg[i];
        if (tid < DE / 4)
            ((float4*)norm_s)[tid] = ((const float4*)(pnorm + bh * DE))[tid];
    }
    __syncthreads();

    const int tx = tid & 15;
    const int ty = tid >> 4;
    const int e0 = tx * 4;     // output column block
    const int g0 = ty * 4;     // row block (phases B/C) or d block (phase D)

    float acc[4][4];           // partial new_kv[d=g0..+3][e=e0..+3]
    float accn[4] = {0.f, 0.f, 0.f, 0.f};
    #pragma unroll
    for (int i = 0; i < 4; i++)
        #pragma unroll
        for (int j = 0; j < 4; j++) acc[i][j] = 0.f;

    const long long baseg = (long long)bh * N_ * DE;
    const int rows_per = N_ / SPLIT;         // 1024
    const int row0 = split * rows_per;

    for (int t0 = 0; t0 < rows_per; t0 += TROWS) {
        // ---------------- Phase A: load + transform -------------------------
        // Flat float4 mapping over the [64 x 64] tile: fully coalesced.
        #pragma unroll
        for (int it = 0; it < 4; it++) {
            int f   = tid + it * 256;   // 0..1023 float4 slots
            int row = f >> 4;           // 0..63
            int c   = f & 15;           // float4 column
            int d4  = c * 4;
            long long g = baseg + (long long)(row0 + t0 + row) * DE + d4;

            float4 kk = *(const float4*)(keys + g);
            float4 qq = *(const float4*)(queries + g);
            float4 vv = *(const float4*)(values + g);

            float4 k4, q4;
            k4.x = elu1(kk.x); k4.y = elu1(kk.y); k4.z = elu1(kk.z); k4.w = elu1(kk.w);
            q4.x = elu1(qq.x); q4.y = elu1(qq.y); q4.z = elu1(qq.z); q4.w = elu1(qq.w);

            *(float4*)(k_s + row * KST + d4) = k4;
            *(float4*)(q_s + row * KST + d4) = q4;
            *(float4*)(v_s + row * KST + d4) = vv;

            float4 n4 = *(const float4*)(norm_s + d4);
            float pk = k4.x * n4.x + k4.y * n4.y + k4.z * n4.z + k4.w * n4.w;
            float pq = q4.x * n4.x + q4.y * n4.y + q4.z * n4.z + q4.w * n4.w;
            // reduce the 16 lanes that share this row
            #pragma unroll
            for (int m = 1; m < 16; m <<= 1) {
                pk += __shfl_xor_sync(0xffffffffu, pk, m);
                pq += __shfl_xor_sync(0xffffffffu, pq, m);
            }
            if (c == 0) {
                rdk_s[row] = __frcp_rn(fmaxf(pk, EPSV));
                rdq_s[row] = __frcp_rn(fmaxf(pq, EPSV));
            }
        }
        __syncthreads();

        // ---------------- Phase B: numer GEMMs vs past_kv -------------------
        // Thread computes 4 rows x 4 cols for both k- and q-numerators.
        float numk[4][4], numq[4][4];
        #pragma unroll
        for (int i = 0; i < 4; i++)
            #pragma unroll
            for (int j = 0; j < 4; j++) { numk[i][j] = 0.f; numq[i][j] = 0.f; }

        const float* kr = k_s + g0 * KST;
        const float* qr = q_s + g0 * KST;
        #pragma unroll 8
        for (int d = 0; d < DE; d++) {
            float4 pv = *(const float4*)(pkv_s + d * DE + e0);
            #pragma unroll
            for (int i = 0; i < 4; i++) {
                float kk = kr[i * KST + d];
                float qq = qr[i * KST + d];
                numk[i][0] += kk * pv.x; numk[i][1] += kk * pv.y;
                numk[i][2] += kk * pv.z; numk[i][3] += kk * pv.w;
                numq[i][0] += qq * pv.x; numq[i][1] += qq * pv.y;
                numq[i][2] += qq * pv.z; numq[i][3] += qq * pv.w;
            }
        }

        // ---------------- Phase C: delta-rule v, gated output ---------------
        #pragma unroll
        for (int i = 0; i < 4; i++) {
            int row = g0 + i;
            float rk = rdk_s[row];
            float rq = rdq_s[row];
            long long g = baseg + (long long)(row0 + t0 + row) * DE + e0;

            float4 o4 = *(const float4*)(outin + g);
            float4 vr = *(float4*)(v_s + row * KST + e0);
            float4 nv, og;
            nv.x = vr.x - numk[i][0] * rk;
            nv.y = vr.y - numk[i][1] * rk;
            nv.z = vr.z - numk[i][2] * rk;
            nv.w = vr.w - numk[i][3] * rk;
            og.x = o4.x * gate + (numq[i][0] * rq) * gate1;
            og.y = o4.y * gate + (numq[i][1] * rq) * gate1;
            og.z = o4.z * gate + (numq[i][2] * rq) * gate1;
            og.w = o4.w * gate + (numq[i][3] * rq) * gate1;

            *(float4*)(v_s + row * KST + e0) = nv;   // corrected v for phase D
            *(float4*)(dout + g) = og;               // out_g
        }
        __syncthreads();

        // ---------------- Phase D: accumulate k^T v (+ norm sum) ------------
        #pragma unroll 8
        for (int r = 0; r < TROWS; r++) {
            float4 k4 = *(const float4*)(k_s + r * KST + g0);
            float4 v4 = *(const float4*)(v_s + r * KST + e0);
            acc[0][0] += k4.x * v4.x; acc[0][1] += k4.x * v4.y;
            acc[0][2] += k4.x * v4.z; acc[0][3] += k4.x * v4.w;
            acc[1][0] += k4.y * v4.x; acc[1][1] += k4.y * v4.y;
            acc[1][2] += k4.y * v4.z; acc[1][3] += k4.y * v4.w;
            acc[2][0] += k4.z * v4.x; acc[2][1] += k4.z * v4.y;
            acc[2][2] += k4.z * v4.z; acc[2][3] += k4.z * v4.w;
            acc[3][0] += k4.w * v4.x; acc[3][1] += k4.w * v4.y;
            acc[3][2] += k4.w * v4.z; acc[3][3] += k4.w * v4.w;
            if (tx == 0) {
                accn[0] += k4.x; accn[1] += k4.y; accn[2] += k4.z; accn[3] += k4.w;
            }
        }
        __syncthreads();
    }

    // ---------------- Epilogue: merge partial new_kv / new_norm -------------
    float* kvo = dout + KV_OFF + (long long)bh * DE * DE;
    #pragma unroll
    for (int i = 0; i < 4; i++)
        #pragma unroll
        for (int j = 0; j < 4; j++)
            atomicAdd(&kvo[(g0 + i) * DE + e0 + j], acc[i][j]);
    if (tx == 0) {
        float* no = dout + NORM_OFF + (long long)bh * DE;
        #pragma unroll
        for (int i = 0; i < 4; i++) atomicAdd(&no[g0 + i], accn[i]);
    }
}

// ---------------------------------------------------------------------------
extern "C" void kernel_launch(void* const* d_in, const int* in_sizes, int n_in,
                              void* d_out, int out_size) {
    const float* keys    = (const float*)d_in[0];
    const float* values  = (const float*)d_in[1];
    const float* queries = (const float*)d_in[2];
    const float* outin   = (const float*)d_in[3];
    const float* pkv     = (const float*)d_in[4];
    const float* pnorm   = (const float*)d_in[5];
    const float* hg      = (const float*)d_in[6];
    float* dout = (float*)d_out;

    // idempotent, not a stream op -> safe under graph capture
    cudaFuncSetAttribute(fw_main, cudaFuncAttributeMaxDynamicSharedMemorySize,
                         SMEM_BYTES);

    fw_init<<<(B_ * H_ * DE * DE + 255) / 256, 256>>>(pkv, pnorm, dout);

    dim3 grid(SPLIT, B_ * H_);
    fw_main<<<grid, 256, SMEM_BYTES>>>(keys, values, queries, outin,
                                       pkv, pnorm, hg, dout);
}

// round 2
// speedup vs baseline: 1.0714x; 1.0714x over previous
#include <cuda_runtime.h>

// Problem constants
#define B_    4
#define H_    16
#define N_    8192
#define DE    64
#define SPLIT 8
#define TROWS 64
#define KST   68         // smem row stride (floats)
#define EPSV  1e-10f

#define KV_OFF   ((long long)B_ * H_ * N_ * DE)
#define NORM_OFF (KV_OFF + (long long)B_ * H_ * DE * DE)
#define SMEM_BYTES ((3 * 64 * KST + 64 * 64 + 64) * 4)   // 68864 B

typedef unsigned long long ull;

union F4 { float4 v; float a[4]; };

// ---- f32x2 packed helpers (Blackwell sm_100+) ------------------------------
__device__ __forceinline__ ull rep2(float x) {
    ull r;
    asm("mov.b64 %0, {%1, %1};" : "=l"(r) : "f"(x));
    return r;
}
__device__ __forceinline__ void ffma2(ull& d, ull a, ull b) {
    asm("fma.rn.f32x2 %0, %1, %2, %3;" : "=l"(d) : "l"(a), "l"(b), "l"(d));
}
__device__ __forceinline__ void unpack2(float& lo, float& hi, ull p) {
    asm("mov.b64 {%0, %1}, %2;" : "=f"(lo), "=f"(hi) : "l"(p));
}

__device__ __forceinline__ float elu1(float x) {
    return x > 0.f ? x + 1.f : __expf(x);
}
__device__ __forceinline__ float4 elu4(float4 x) {
    float4 r;
    r.x = elu1(x.x); r.y = elu1(x.y); r.z = elu1(x.z); r.w = elu1(x.w);
    return r;
}

// ---------------------------------------------------------------------------
__global__ void fw_init(const float* __restrict__ pkv,
                        const float* __restrict__ pnorm,
                        float* __restrict__ dout) {
    int i = blockIdx.x * blockDim.x + threadIdx.x;
    if (i < B_ * H_ * DE * DE) dout[KV_OFF + i]   = pkv[i];
    if (i < B_ * H_ * DE)      dout[NORM_OFF + i] = pnorm[i];
}

// ---------------------------------------------------------------------------
// 256 threads. tx = tid&7 -> cols {4tx..4tx+3} U {32+4tx..32+4tx+3}
//              ty = tid>>3 -> rows {2ty, 2ty+1} (phases B/C), d's {2ty,2ty+1} (D)
// ---------------------------------------------------------------------------
__global__ __launch_bounds__(256, 2)
void fw_main(const float* __restrict__ keys,
             const float* __restrict__ values,
             const float* __restrict__ queries,
             const float* __restrict__ outin,
             const float* __restrict__ pkv,
             const float* __restrict__ pnorm,
             const float* __restrict__ hg,
             float* __restrict__ dout)
{
    extern __shared__ float sm[];
    float* k_s    = sm;                  // [64][KST]
    float* q_s    = k_s + 64 * KST;      // [64][KST]
    float* v_s    = q_s + 64 * KST;      // [64][KST] (corrected v, written in C)
    float* pkv_s  = v_s + 64 * KST;      // [64][64]
    float* norm_s = pkv_s + 64 * 64;     // [64]

    const int tid   = threadIdx.x;
    const int split = blockIdx.x;
    const int bh    = blockIdx.y;
    const int h     = bh & (H_ - 1);

    const float gate  = 1.f / (1.f + __expf(-hg[h]));
    const float gate1 = 1.f - gate;

    // Stage past_kv / past_norm
    {
        const float4* pg = (const float4*)(pkv + (long long)bh * DE * DE);
        for (int i = tid; i < DE * DE / 4; i += 256)
            ((float4*)pkv_s)[i] = pg[i];
        if (tid < DE / 4)
            ((float4*)norm_s)[tid] = ((const float4*)(pnorm + bh * DE))[tid];
    }

    const int tx  = tid & 7;
    const int ty  = tid >> 3;
    const int e0a = tx * 4;
    const int e0b = 32 + tx * 4;
    const int r0  = ty * 2;     // rows (B/C) / d-block (D)

    // Cross-tile accumulators: partial new_kv[d0..d0+1][8 cols] and norm sums
    ull acc[2][4];
    #pragma unroll
    for (int i = 0; i < 2; i++)
        #pragma unroll
        for (int p = 0; p < 4; p++) acc[i][p] = 0ULL;
    float accn0 = 0.f, accn1 = 0.f;

    const long long baseg = (long long)bh * N_ * DE;
    const int rows_per = N_ / SPLIT;     // 1024
    const int row0 = split * rows_per;

    // ---- Prologue: prefetch tile 0's k,q into registers --------------------
    float4 kpre[4], qpre[4];
    #pragma unroll
    for (int it = 0; it < 4; it++) {
        int f = tid + it * 256;
        int row = f >> 4, c = f & 15;
        long long g = baseg + (long long)(row0 + row) * DE + c * 4;
        kpre[it] = *(const float4*)(keys + g);
        qpre[it] = *(const float4*)(queries + g);
    }
    __syncthreads();   // pkv_s / norm_s ready

    #pragma unroll 1
    for (int t0 = 0; t0 < rows_per; t0 += TROWS) {
        // ---------------- Phase A: elu + store, then prefetch next ----------
        #pragma unroll
        for (int it = 0; it < 4; it++) {
            int f = tid + it * 256;
            int row = f >> 4, c = f & 15;
            *(float4*)(k_s + row * KST + c * 4) = elu4(kpre[it]);
            *(float4*)(q_s + row * KST + c * 4) = elu4(qpre[it]);
        }
        if (t0 + TROWS < rows_per) {
            #pragma unroll
            for (int it = 0; it < 4; it++) {
                int f = tid + it * 256;
                int row = f >> 4, c = f & 15;
                long long g = baseg + (long long)(row0 + t0 + TROWS + row) * DE + c * 4;
                kpre[it] = *(const float4*)(keys + g);
                qpre[it] = *(const float4*)(queries + g);
            }
        }
        __syncthreads();

        // ---------------- Phase B: numer GEMMs + denominators (FFMA2) -------
        ull numk[2][4], numq[2][4];
        #pragma unroll
        for (int i = 0; i < 2; i++)
            #pragma unroll
            for (int p = 0; p < 4; p++) { numk[i][p] = 0ULL; numq[i][p] = 0ULL; }
        float denk[2] = {0.f, 0.f}, denq[2] = {0.f, 0.f};

        const float* kr0 = k_s + r0 * KST;
        const float* kr1 = kr0 + KST;
        const float* qr0 = q_s + r0 * KST;
        const float* qr1 = qr0 + KST;

        #pragma unroll 4
        for (int dq = 0; dq < DE; dq += 4) {
            F4 ka, kb, qa, qb, nn;
            ka.v = *(const float4*)(kr0 + dq);
            kb.v = *(const float4*)(kr1 + dq);
            qa.v = *(const float4*)(qr0 + dq);
            qb.v = *(const float4*)(qr1 + dq);
            nn.v = *(const float4*)(norm_s + dq);
            #pragma unroll
            for (int j = 0; j < 4; j++) {
                const float* pvp = pkv_s + (dq + j) * DE;
                ull pv0 = *(const ull*)(pvp + e0a);
                ull pv1 = *(const ull*)(pvp + e0a + 2);
                ull pv2 = *(const ull*)(pvp + e0b);
                ull pv3 = *(const ull*)(pvp + e0b + 2);
                ull k0 = rep2(ka.a[j]), k1 = rep2(kb.a[j]);
                ull q0 = rep2(qa.a[j]), q1 = rep2(qb.a[j]);
                ffma2(numk[0][0], k0, pv0); ffma2(numk[0][1], k0, pv1);
                ffma2(numk[0][2], k0, pv2); ffma2(numk[0][3], k0, pv3);
                ffma2(numk[1][0], k1, pv0); ffma2(numk[1][1], k1, pv1);
                ffma2(numk[1][2], k1, pv2); ffma2(numk[1][3], k1, pv3);
                ffma2(numq[0][0], q0, pv0); ffma2(numq[0][1], q0, pv1);
                ffma2(numq[0][2], q0, pv2); ffma2(numq[0][3], q0, pv3);
                ffma2(numq[1][0], q1, pv0); ffma2(numq[1][1], q1, pv1);
                ffma2(numq[1][2], q1, pv2); ffma2(numq[1][3], q1, pv3);
                denk[0] = fmaf(ka.a[j], nn.a[j], denk[0]);
                denk[1] = fmaf(kb.a[j], nn.a[j], denk[1]);
                denq[0] = fmaf(qa.a[j], nn.a[j], denq[0]);
                denq[1] = fmaf(qb.a[j], nn.a[j], denq[1]);
            }
        }

        // ---------------- Phase C: delta v, gated output --------------------
        #pragma unroll
        for (int i = 0; i < 2; i++) {
            int row = r0 + i;
            long long g = baseg + (long long)(row0 + t0 + row) * DE;
            float rk = __frcp_rn(fmaxf(denk[i], EPSV));
            float rq = __frcp_rn(fmaxf(denq[i], EPSV));

            F4 vA, vB, oA, oB;
            vA.v = *(const float4*)(values + g + e0a);
            vB.v = *(const float4*)(values + g + e0b);
            oA.v = *(const float4*)(outin + g + e0a);
            oB.v = *(const float4*)(outin + g + e0b);

            float nk[8], nq[8];
            unpack2(nk[0], nk[1], numk[i][0]); unpack2(nk[2], nk[3], numk[i][1]);
            unpack2(nk[4], nk[5], numk[i][2]); unpack2(nk[6], nk[7], numk[i][3]);
            unpack2(nq[0], nq[1], numq[i][0]); unpack2(nq[2], nq[3], numq[i][1]);
            unpack2(nq[4], nq[5], numq[i][2]); unpack2(nq[6], nq[7], numq[i][3]);

            F4 nvA, nvB, ogA, ogB;
            #pragma unroll
            for (int j = 0; j < 4; j++) {
                nvA.a[j] = vA.a[j] - nk[j] * rk;
                nvB.a[j] = vB.a[j] - nk[4 + j] * rk;
                ogA.a[j] = oA.a[j] * gate + (nq[j] * rq) * gate1;
                ogB.a[j] = oB.a[j] * gate + (nq[4 + j] * rq) * gate1;
            }
            *(float4*)(dout + g + e0a) = ogA.v;
            *(float4*)(dout + g + e0b) = ogB.v;
            *(float4*)(v_s + row * KST + e0a) = nvA.v;
            *(float4*)(v_s + row * KST + e0b) = nvB.v;
        }
        __syncthreads();

        // ---------------- Phase D: accumulate k^T v (+ norm) (FFMA2) --------
        #pragma unroll 4
        for (int r = 0; r < TROWS; r++) {
            const float* krow = k_s + r * KST;
            const float* vrow = v_s + r * KST;
            float k0s = krow[r0], k1s = krow[r0 + 1];
            ull v0 = *(const ull*)(vrow + e0a);
            ull v1 = *(const ull*)(vrow + e0a + 2);
            ull v2 = *(const ull*)(vrow + e0b);
            ull v3 = *(const ull*)(vrow + e0b + 2);
            ull k0 = rep2(k0s), k1 = rep2(k1s);
            ffma2(acc[0][0], k0, v0); ffma2(acc[0][1], k0, v1);
            ffma2(acc[0][2], k0, v2); ffma2(acc[0][3], k0, v3);
            ffma2(acc[1][0], k1, v0); ffma2(acc[1][1], k1, v1);
            ffma2(acc[1][2], k1, v2); ffma2(acc[1][3], k1, v3);
            if (tx == 0) { accn0 += k0s; accn1 += k1s; }
        }
        __syncthreads();
    }

    // ---- Epilogue: merge partials ------------------------------------------
    float* kvo = dout + KV_OFF + (long long)bh * DE * DE;
    #pragma unroll
    for (int i = 0; i < 2; i++) {
        float lo, hi;
        unpack2(lo, hi, acc[i][0]);
        atomicAdd(&kvo[(r0 + i) * DE + e0a + 0], lo);
        atomicAdd(&kvo[(r0 + i) * DE + e0a + 1], hi);
        unpack2(lo, hi, acc[i][1]);
        atomicAdd(&kvo[(r0 + i) * DE + e0a + 2], lo);
        atomicAdd(&kvo[(r0 + i) * DE + e0a + 3], hi);
        unpack2(lo, hi, acc[i][2]);
        atomicAdd(&kvo[(r0 + i) * DE + e0b + 0], lo);
        atomicAdd(&kvo[(r0 + i) * DE + e0b + 1], hi);
        unpack2(lo, hi, acc[i][3]);
        atomicAdd(&kvo[(r0 + i) * DE + e0b + 2], lo);
        atomicAdd(&kvo[(r0 + i) * DE + e0b + 3], hi);
    }
    if (tx == 0) {
        float* no = dout + NORM_OFF + (long long)bh * DE;
        atomicAdd(&no[r0], accn0);
        atomicAdd(&no[r0 + 1], accn1);
    }
}

// ---------------------------------------------------------------------------
extern "C" void kernel_launch(void* const* d_in, const int* in_sizes, int n_in,
                              void* d_out, int out_size) {
    const float* keys    = (const float*)d_in[0];
    const float* values  = (const float*)d_in[1];
    const float* queries = (const float*)d_in[2];
    const float* outin   = (const float*)d_in[3];
    const float* pkv     = (const float*)d_in[4];
    const float* pnorm   = (const float*)d_in[5];
    const float* hg      = (const float*)d_in[6];
    float* dout = (float*)d_out;

    cudaFuncSetAttribute(fw_main, cudaFuncAttributeMaxDynamicSharedMemorySize,
                         SMEM_BYTES);

    fw_init<<<(B_ * H_ * DE * DE + 255) / 256, 256>>>(pkv, pnorm, dout);

    dim3 grid(SPLIT, B_ * H_);
    fw_main<<<grid, 256, SMEM_BYTES>>>(keys, values, queries, outin,
                                       pkv, pnorm, hg, dout);
}